// round 1
// baseline (speedup 1.0000x reference)
#include <cuda_runtime.h>
#include <cuda_bf16.h>

// EntityLinker edge-MLP, fused 3-layer, FFMA baseline.
// Per CTA: TE=64 edges. Layer1: [64,512]@[512,256]; edge_input columns are
// synthesized on the fly from smem-resident h_i/h_j (seg 0..3 = hi, hj, |hi-hj|, hi*hj).
// Layer2: [64,256]@[256,128]. Layer3: [64,128]@[128,2].

#define H 128
#define TE 64
#define NTHREADS 256

__global__ __launch_bounds__(NTHREADS, 1)
void edge_mlp_kernel(const float* __restrict__ node,
                     const int*   __restrict__ src,
                     const int*   __restrict__ dst,
                     const float* __restrict__ W1, const float* __restrict__ b1,
                     const float* __restrict__ W2, const float* __restrict__ b2,
                     const float* __restrict__ W3, const float* __restrict__ b3,
                     float* __restrict__ out, int E)
{
    extern __shared__ float smem[];
    float* s_hi = smem;                 // [64][128]  32 KB
    float* s_hj = s_hi + TE * H;        // [64][128]  32 KB
    float* s_w  = s_hj + TE * H;        // [128][128] 64 KB (weight K-tile)
    float* s_x1 = s_w + 128 * 128;      // [64][256]  64 KB
    // total 49152 floats = 192 KB

    const int tid   = threadIdx.x;
    const int e0    = blockIdx.x * TE;
    const int nedge = min(TE, E - e0);

    // ---- gather h_i, h_j (float4) ----
    for (int idx = tid; idx < TE * (H / 4); idx += NTHREADS) {
        int m  = idx / (H / 4);
        int k4 = idx % (H / 4);
        int e  = e0 + m;
        int si = (m < nedge) ? src[e] : 0;
        int di = (m < nedge) ? dst[e] : 0;
        float4 vi = ((const float4*)node)[(size_t)si * (H / 4) + k4];
        float4 vj = ((const float4*)node)[(size_t)di * (H / 4) + k4];
        ((float4*)s_hi)[m * (H / 4) + k4] = vi;
        ((float4*)s_hj)[m * (H / 4) + k4] = vj;
    }

    // thread tile: 16 n-blocks x 16 m-blocks; each thread owns 4(M) x 8(N)
    const int tx = tid & 15;        // n block
    const int ty = tid >> 4;        // m block
    const int m0 = ty * 4;
    const int n0 = tx * 8;

    // ================= Layer 1 =================
    for (int nb = 0; nb < 2; nb++) {
        float acc[4][8];
        #pragma unroll
        for (int i = 0; i < 4; i++)
            #pragma unroll
            for (int j = 0; j < 8; j++) acc[i][j] = 0.f;

        #pragma unroll
        for (int seg = 0; seg < 4; seg++) {
            __syncthreads();  // protect s_w reuse (also covers gather at seg=0,nb=0)
            // load W1 tile: rows [seg*128, +128), cols [nb*128, +128)
            for (int idx = tid; idx < 128 * 32; idx += NTHREADS) {
                int r  = idx >> 5;
                int c4 = idx & 31;
                ((float4*)(s_w + r * 128))[c4] =
                    ((const float4*)(W1 + (size_t)(seg * 128 + r) * 256 + nb * 128))[c4];
            }
            __syncthreads();

            for (int kk = 0; kk < 128; kk += 4) {
                float4 ai[4], aj[4];
                #pragma unroll
                for (int i = 0; i < 4; i++) {
                    ai[i] = *((float4*)(s_hi + (m0 + i) * H + kk));
                    aj[i] = *((float4*)(s_hj + (m0 + i) * H + kk));
                }
                #pragma unroll
                for (int u = 0; u < 4; u++) {
                    float a[4];
                    #pragma unroll
                    for (int i = 0; i < 4; i++) {
                        float vhi = ((const float*)&ai[i])[u];
                        float vhj = ((const float*)&aj[i])[u];
                        a[i] = (seg == 0) ? vhi
                             : (seg == 1) ? vhj
                             : (seg == 2) ? fabsf(vhi - vhj)
                                          : vhi * vhj;
                    }
                    float4 bv0 = *((float4*)(s_w + (kk + u) * 128 + n0));
                    float4 bv1 = *((float4*)(s_w + (kk + u) * 128 + n0 + 4));
                    float b[8] = {bv0.x, bv0.y, bv0.z, bv0.w, bv1.x, bv1.y, bv1.z, bv1.w};
                    #pragma unroll
                    for (int i = 0; i < 4; i++)
                        #pragma unroll
                        for (int j = 0; j < 8; j++)
                            acc[i][j] += a[i] * b[j];
                }
            }
        }
        // relu + bias -> s_x1
        #pragma unroll
        for (int i = 0; i < 4; i++)
            #pragma unroll
            for (int j = 0; j < 8; j++) {
                float v = acc[i][j] + b1[nb * 128 + n0 + j];
                s_x1[(m0 + i) * 256 + nb * 128 + n0 + j] = fmaxf(v, 0.f);
            }
    }
    __syncthreads();

    // ================= Layer 2 =================
    {
        float acc[4][8];
        #pragma unroll
        for (int i = 0; i < 4; i++)
            #pragma unroll
            for (int j = 0; j < 8; j++) acc[i][j] = 0.f;

        #pragma unroll
        for (int seg = 0; seg < 2; seg++) {
            __syncthreads();
            for (int idx = tid; idx < 128 * 32; idx += NTHREADS) {
                int r  = idx >> 5;
                int c4 = idx & 31;
                ((float4*)(s_w + r * 128))[c4] =
                    ((const float4*)(W2 + (size_t)(seg * 128 + r) * 128))[c4];
            }
            __syncthreads();

            for (int kk = 0; kk < 128; kk += 4) {
                float4 av[4];
                #pragma unroll
                for (int i = 0; i < 4; i++)
                    av[i] = *((float4*)(s_x1 + (m0 + i) * 256 + seg * 128 + kk));
                #pragma unroll
                for (int u = 0; u < 4; u++) {
                    float4 bv0 = *((float4*)(s_w + (kk + u) * 128 + n0));
                    float4 bv1 = *((float4*)(s_w + (kk + u) * 128 + n0 + 4));
                    float b[8] = {bv0.x, bv0.y, bv0.z, bv0.w, bv1.x, bv1.y, bv1.z, bv1.w};
                    #pragma unroll
                    for (int i = 0; i < 4; i++) {
                        float a = ((const float*)&av[i])[u];
                        #pragma unroll
                        for (int j = 0; j < 8; j++)
                            acc[i][j] += a * b[j];
                    }
                }
            }
        }
        __syncthreads();  // everyone done reading s_x1 & s_hi consumers before overwrite
        // relu + bias -> x2 stored into s_hi region ([64][128])
        #pragma unroll
        for (int i = 0; i < 4; i++)
            #pragma unroll
            for (int j = 0; j < 8; j++) {
                float v = acc[i][j] + b2[n0 + j];
                s_hi[(m0 + i) * H + n0 + j] = fmaxf(v, 0.f);
            }
    }
    __syncthreads();

    // ================= Layer 3 =================
    if (tid < TE * 2) {
        int m = tid >> 1;
        int c = tid & 1;
        if (m < nedge) {
            float sum = b3[c];
            #pragma unroll 8
            for (int k = 0; k < H; k++)
                sum += s_hi[m * H + k] * W3[k * 2 + c];
            out[(size_t)(e0 + m) * 2 + c] = sum;
        }
    }
}

extern "C" void kernel_launch(void* const* d_in, const int* in_sizes, int n_in,
                              void* d_out, int out_size)
{
    const float* node = (const float*)d_in[0];
    const int*   src  = (const int*)  d_in[1];
    const int*   dst  = (const int*)  d_in[2];
    const float* W1   = (const float*)d_in[3];
    const float* b1   = (const float*)d_in[4];
    const float* W2   = (const float*)d_in[5];
    const float* b2   = (const float*)d_in[6];
    const float* W3   = (const float*)d_in[7];
    const float* b3   = (const float*)d_in[8];
    float* out = (float*)d_out;

    const int E = in_sizes[1];
    const int smem_bytes = 49152 * (int)sizeof(float);  // 192 KB

    cudaFuncSetAttribute(edge_mlp_kernel,
                         cudaFuncAttributeMaxDynamicSharedMemorySize, smem_bytes);

    const int grid = (E + TE - 1) / TE;
    edge_mlp_kernel<<<grid, NTHREADS, smem_bytes>>>(
        node, src, dst, W1, b1, W2, b2, W3, b3, out, E);
}

// round 5
// speedup vs baseline: 4.8310x; 4.8310x over previous
#include <cuda_runtime.h>
#include <cstdint>

#define H 128
#define TE 128
#define NT 256

// Pre-rounded (RNA->tf32) weights, original [K][N] layout. Static scratch, no alloc.
__device__ float g_W1R[512 * 256];
__device__ float g_W2R[256 * 128];

// ---------------- helpers ----------------
__device__ __forceinline__ uint32_t smem_u32(const void* p) {
    uint32_t a;
    asm("{ .reg .u64 t; cvta.to.shared.u64 t, %1; cvt.u32.u64 %0, t; }" : "=r"(a) : "l"(p));
    return a;
}
__device__ __forceinline__ uint32_t rna(float x) {
    uint32_t r;
    asm("cvt.rna.tf32.f32 %0, %1;" : "=r"(r) : "f"(x));
    return r;
}
#define CP_ASYNC16(dst_u32, src_ptr) \
    asm volatile("cp.async.cg.shared.global [%0], [%1], 16;" :: "r"(dst_u32), "l"(src_ptr) : "memory")
#define CP_COMMIT() asm volatile("cp.async.commit_group;" ::: "memory")
#define CP_WAIT(n)  asm volatile("cp.async.wait_group %0;" :: "n"(n) : "memory")

__device__ __forceinline__ void mma8(float* c, const uint32_t* a, uint32_t b0, uint32_t b1) {
    asm volatile(
        "mma.sync.aligned.m16n8k8.row.col.f32.tf32.tf32.f32 "
        "{%0,%1,%2,%3}, {%4,%5,%6,%7}, {%8,%9}, {%0,%1,%2,%3};"
        : "+f"(c[0]), "+f"(c[1]), "+f"(c[2]), "+f"(c[3])
        : "r"(a[0]), "r"(a[1]), "r"(a[2]), "r"(a[3]), "r"(b0), "r"(b1));
}

// XOR swizzle: row-stride 128 floats, 4-float blocks XORed by (row&7). Conflict-free
// for the mma A-quad LDS pattern and for float4 gather stores.
__device__ __forceinline__ int swz(int r, int c) {
    return r * 128 + ((((c >> 2) ^ (r & 7)) << 2) | (c & 3));
}

// ---------------- smem layout (float offsets) ----------------
#define OFF_HI 0          // [128][128] swizzled
#define OFF_HJ 16384      // [128][128] swizzled
#define OFF_WX 32768      // union: L1 B dbuf [2][4 seg][16 k][128 n] / x1half [128][128] / x2
#define OFF_W2 49152      // L2 B dbuf [2][32 k][128 n]
#define OFF_B1 57344      // [256]
#define OFF_B2 57600      // [128]
#define OFF_W3 57728      // [256] (W3 row-major [128][2])
#define OFF_B3 57984      // [2]
#define SMEM_FLOATS 57986
#define SMEM_BYTES (SMEM_FLOATS * 4)

// ---------------- prep: RNA-round weights ----------------
__global__ void prep_kernel(const float* __restrict__ W1, const float* __restrict__ W2) {
    int i = blockIdx.x * blockDim.x + threadIdx.x;
    if (i < 512 * 256) {
        g_W1R[i] = __uint_as_float(rna(W1[i]));
    } else {
        int j = i - 512 * 256;
        if (j < 256 * 128) g_W2R[j] = __uint_as_float(rna(W2[j]));
    }
}

// ---------------- chunk prefetch (cp.async) ----------------
// Layer1 chunk c (k-local [16c,16c+16) for all 4 segs), n-half h, dbuf d: 64 rows x 128 n.
__device__ __forceinline__ void issue_l1_chunk(uint32_t smb, int tid, int h, int c, int d) {
    #pragma unroll
    for (int i = 0; i < 8; i++) {
        int idx = tid + i * NT;
        int rf = idx >> 5;          // 0..63 = seg*16 + kk
        int c4 = idx & 31;
        int seg = rf >> 4, kk = rf & 15;
        const float* srcp = g_W1R + (size_t)(seg * 128 + c * 16 + kk) * 256 + h * 128 + c4 * 4;
        int R = d * 64 + rf;
        uint32_t dstf = (uint32_t)(OFF_WX + R * 128 + ((c4 ^ (kk & 7)) << 2));
        CP_ASYNC16(smb + dstf * 4, srcp);
    }
}
// Layer2 chunk c (k rows [h*128+32c, +32)), dbuf d: 32 rows x 128 n.
__device__ __forceinline__ void issue_l2_chunk(uint32_t smb, int tid, int h, int c, int d) {
    #pragma unroll
    for (int i = 0; i < 4; i++) {
        int idx = tid + i * NT;
        int kk = idx >> 5;          // 0..31
        int c4 = idx & 31;
        const float* srcp = g_W2R + (size_t)(h * 128 + c * 32 + kk) * 128 + c4 * 4;
        int R = d * 32 + kk;
        uint32_t dstf = (uint32_t)(OFF_W2 + R * 128 + ((c4 ^ (kk & 7)) << 2));
        CP_ASYNC16(smb + dstf * 4, srcp);
    }
}

// ---------------- main fused MLP ----------------
__global__ __launch_bounds__(NT, 1)
void edge_mlp_mma(const float* __restrict__ node,
                  const int*   __restrict__ src,
                  const int*   __restrict__ dst,
                  const float* __restrict__ b1,
                  const float* __restrict__ b2,
                  const float* __restrict__ W3,
                  const float* __restrict__ b3,
                  float* __restrict__ out, int E)
{
    extern __shared__ float sm[];
    const uint32_t smb = smem_u32(sm);

    const int tid = threadIdx.x;
    const int lane = tid & 31;
    const int g = lane >> 2, t = lane & 3;       // mma quad coords
    const int wid = tid >> 5;
    const int wm = wid >> 2, wn = wid & 3;       // warp grid 2(M) x 4(N)
    const int e0 = blockIdx.x * TE;
    const int nedge = min(TE, E - e0);

    // prefetch first L1 weight chunk; overlaps with gather
    issue_l1_chunk(smb, tid, 0, 0, 0);
    CP_COMMIT();

    // ---- gather h_i / h_j (32 threads per edge row, float4, swizzled STS) ----
    #pragma unroll 4
    for (int i = 0; i < 16; i++) {
        int idx = tid + i * NT;
        int m = idx >> 5, c4 = idx & 31;
        int e = min(e0 + m, E - 1);
        int si = src[e], di = dst[e];
        float4 vi = ((const float4*)node)[(size_t)si * 32 + c4];
        float4 vj = ((const float4*)node)[(size_t)di * 32 + c4];
        int pb = (c4 ^ (m & 7)) << 2;
        *(float4*)(sm + OFF_HI + m * 128 + pb) = vi;
        *(float4*)(sm + OFF_HJ + m * 128 + pb) = vj;
    }
    for (int i = tid; i < 256; i += NT) sm[OFF_B1 + i] = b1[i];
    for (int i = tid; i < 128; i += NT) sm[OFF_B2 + i] = b2[i];
    for (int i = tid; i < 256; i += NT) sm[OFF_W3 + i] = W3[i];
    if (tid < 2) sm[OFF_B3 + tid] = b3[tid];
    __syncthreads();

    // layer-2 accumulators, init with b2 (persist across both halves)
    float accL2[64];
    #pragma unroll
    for (int mt = 0; mt < 4; mt++)
        #pragma unroll
        for (int nt = 0; nt < 4; nt++) {
            int col = wn * 32 + nt * 8 + 2 * t;
            float v0 = sm[OFF_B2 + col], v1 = sm[OFF_B2 + col + 1];
            float* A = &accL2[(mt * 4 + nt) * 4];
            A[0] = v0; A[1] = v1; A[2] = v0; A[3] = v1;
        }

    for (int h = 0; h < 2; h++) {
        // layer-1 accumulators, init with b1 slice
        float accL1[64];
        #pragma unroll
        for (int mt = 0; mt < 4; mt++)
            #pragma unroll
            for (int nt = 0; nt < 4; nt++) {
                int col = h * 128 + wn * 32 + nt * 8 + 2 * t;
                float v0 = sm[OFF_B1 + col], v1 = sm[OFF_B1 + col + 1];
                float* A = &accL1[(mt * 4 + nt) * 4];
                A[0] = v0; A[1] = v1; A[2] = v0; A[3] = v1;
            }

        if (h == 1) {   // L2h0 finished (trailing sync) -> s_wx free for L1 B chunks
            issue_l1_chunk(smb, tid, 1, 0, 0);
            CP_COMMIT();
        }

        // ======== layer 1: 8 chunks of 16 k-rows (x4 segs), dbuf ========
        for (int c = 0; c < 8; c++) {
            if (c < 7) { issue_l1_chunk(smb, tid, h, c + 1, (c + 1) & 1); CP_COMMIT(); CP_WAIT(1); }
            else       { CP_WAIT(0); }
            __syncthreads();
            const int d = c & 1;

            #pragma unroll
            for (int ks = 0; ks < 2; ks++) {
                const int kb = c * 16 + ks * 8;
                float hiv[16], hjv[16];
                #pragma unroll
                for (int mt = 0; mt < 4; mt++) {
                    int r = wm * 64 + mt * 16 + g;
                    int cc0 = kb + t, cc1 = kb + t + 4;
                    hiv[mt * 4 + 0] = sm[OFF_HI + swz(r,     cc0)];
                    hiv[mt * 4 + 1] = sm[OFF_HI + swz(r + 8, cc0)];
                    hiv[mt * 4 + 2] = sm[OFF_HI + swz(r,     cc1)];
                    hiv[mt * 4 + 3] = sm[OFF_HI + swz(r + 8, cc1)];
                    hjv[mt * 4 + 0] = sm[OFF_HJ + swz(r,     cc0)];
                    hjv[mt * 4 + 1] = sm[OFF_HJ + swz(r + 8, cc0)];
                    hjv[mt * 4 + 2] = sm[OFF_HJ + swz(r,     cc1)];
                    hjv[mt * 4 + 3] = sm[OFF_HJ + swz(r + 8, cc1)];
                }
                #pragma unroll
                for (int seg = 0; seg < 4; seg++) {
                    uint32_t a[16];
                    #pragma unroll
                    for (int x = 0; x < 16; x++) {
                        float hi = hiv[x], hj = hjv[x];
                        float v = (seg == 0) ? hi
                                : (seg == 1) ? hj
                                : (seg == 2) ? fabsf(hi - hj)
                                             : hi * hj;
                        a[x] = rna(v);
                    }
                    uint32_t bb[8];
                    #pragma unroll
                    for (int nt = 0; nt < 4; nt++) {
                        int n = wn * 32 + nt * 8 + g;
                        int kr0 = ks * 8 + t, kr1 = kr0 + 4;
                        int R0 = d * 64 + seg * 16 + kr0;
                        int R1 = d * 64 + seg * 16 + kr1;
                        bb[nt * 2 + 0] = __float_as_uint(
                            sm[OFF_WX + R0 * 128 + ((((n >> 2) ^ (kr0 & 7)) << 2) | (n & 3))]);
                        bb[nt * 2 + 1] = __float_as_uint(
                            sm[OFF_WX + R1 * 128 + ((((n >> 2) ^ (kr1 & 7)) << 2) | (n & 3))]);
                    }
                    #pragma unroll
                    for (int mt = 0; mt < 4; mt++)
                        #pragma unroll
                        for (int nt = 0; nt < 4; nt++)
                            mma8(&accL1[(mt * 4 + nt) * 4], &a[mt * 4], bb[nt * 2], bb[nt * 2 + 1]);
                }
            }
            __syncthreads();
        }

        // prefetch first L2 chunk while storing x1
        issue_l2_chunk(smb, tid, h, 0, 0);
        CP_COMMIT();

        // x1 = rna(relu(acc)) -> s_wx (swizzled [128][128])
        #pragma unroll
        for (int mt = 0; mt < 4; mt++) {
            int r = wm * 64 + mt * 16 + g;
            #pragma unroll
            for (int nt = 0; nt < 4; nt++) {
                int col = wn * 32 + nt * 8 + 2 * t;
                float* A = &accL1[(mt * 4 + nt) * 4];
                sm[OFF_WX + swz(r,     col    )] = __uint_as_float(rna(fmaxf(A[0], 0.f)));
                sm[OFF_WX + swz(r,     col + 1)] = __uint_as_float(rna(fmaxf(A[1], 0.f)));
                sm[OFF_WX + swz(r + 8, col    )] = __uint_as_float(rna(fmaxf(A[2], 0.f)));
                sm[OFF_WX + swz(r + 8, col + 1)] = __uint_as_float(rna(fmaxf(A[3], 0.f)));
            }
        }
        __syncthreads();

        // ======== layer 2: 4 chunks of 32 k-rows, dbuf ========
        for (int c = 0; c < 4; c++) {
            if (c < 3) { issue_l2_chunk(smb, tid, h, c + 1, (c + 1) & 1); CP_COMMIT(); CP_WAIT(1); }
            else       { CP_WAIT(0); }
            __syncthreads();
            const int d = c & 1;

            #pragma unroll
            for (int ks = 0; ks < 4; ks++) {
                const int kb = c * 32 + ks * 8;
                uint32_t a[16];
                #pragma unroll
                for (int mt = 0; mt < 4; mt++) {
                    int r = wm * 64 + mt * 16 + g;
                    int cc0 = kb + t, cc1 = kb + t + 4;
                    a[mt * 4 + 0] = __float_as_uint(sm[OFF_WX + swz(r,     cc0)]);
                    a[mt * 4 + 1] = __float_as_uint(sm[OFF_WX + swz(r + 8, cc0)]);
                    a[mt * 4 + 2] = __float_as_uint(sm[OFF_WX + swz(r,     cc1)]);
                    a[mt * 4 + 3] = __float_as_uint(sm[OFF_WX + swz(r + 8, cc1)]);
                }
                uint32_t bb[8];
                #pragma unroll
                for (int nt = 0; nt < 4; nt++) {
                    int n = wn * 32 + nt * 8 + g;
                    int kr0 = ks * 8 + t, kr1 = kr0 + 4;
                    bb[nt * 2 + 0] = __float_as_uint(
                        sm[OFF_W2 + (d * 32 + kr0) * 128 + ((((n >> 2) ^ (kr0 & 7)) << 2) | (n & 3))]);
                    bb[nt * 2 + 1] = __float_as_uint(
                        sm[OFF_W2 + (d * 32 + kr1) * 128 + ((((n >> 2) ^ (kr1 & 7)) << 2) | (n & 3))]);
                }
                #pragma unroll
                for (int mt = 0; mt < 4; mt++)
                    #pragma unroll
                    for (int nt = 0; nt < 4; nt++)
                        mma8(&accL2[(mt * 4 + nt) * 4], &a[mt * 4], bb[nt * 2], bb[nt * 2 + 1]);
            }
            __syncthreads();
        }
    }

    // ======== epilogue: x2 = relu(accL2) -> s_wx, then layer 3 ========
    #pragma unroll
    for (int mt = 0; mt < 4; mt++) {
        int r = wm * 64 + mt * 16 + g;
        #pragma unroll
        for (int nt = 0; nt < 4; nt++) {
            int col = wn * 32 + nt * 8 + 2 * t;
            float* A = &accL2[(mt * 4 + nt) * 4];
            sm[OFF_WX + swz(r,     col    )] = fmaxf(A[0], 0.f);
            sm[OFF_WX + swz(r,     col + 1)] = fmaxf(A[1], 0.f);
            sm[OFF_WX + swz(r + 8, col    )] = fmaxf(A[2], 0.f);
            sm[OFF_WX + swz(r + 8, col + 1)] = fmaxf(A[3], 0.f);
        }
    }
    __syncthreads();

    {
        int m = tid >> 1, cc = tid & 1;
        float sum = sm[OFF_B3 + cc];
        int k0 = (lane << 2) & 127;   // stagger to dodge bank conflicts
        #pragma unroll 8
        for (int i = 0; i < 128; i++) {
            int k = (k0 + i) & 127;
            sum += sm[OFF_WX + swz(m, k)] * sm[OFF_W3 + 2 * k + cc];
        }
        if (m < nedge) out[(size_t)(e0 + m) * 2 + cc] = sum;
    }
}

extern "C" void kernel_launch(void* const* d_in, const int* in_sizes, int n_in,
                              void* d_out, int out_size)
{
    const float* node = (const float*)d_in[0];
    const int*   src  = (const int*)  d_in[1];
    const int*   dst  = (const int*)  d_in[2];
    const float* W1   = (const float*)d_in[3];
    const float* b1   = (const float*)d_in[4];
    const float* W2   = (const float*)d_in[5];
    const float* b2   = (const float*)d_in[6];
    const float* W3   = (const float*)d_in[7];
    const float* b3   = (const float*)d_in[8];
    float* out = (float*)d_out;

    const int E = in_sizes[1];

    {
        int total = 512 * 256 + 256 * 128;
        prep_kernel<<<(total + 255) / 256, 256>>>(W1, W2);
    }

    cudaFuncSetAttribute(edge_mlp_mma,
                         cudaFuncAttributeMaxDynamicSharedMemorySize, SMEM_BYTES);

    const int grid = (E + TE - 1) / TE;
    edge_mlp_mma<<<grid, NT, SMEM_BYTES>>>(node, src, dst, b1, b2, W3, b3, out, E);
}

// round 6
// speedup vs baseline: 10.1858x; 2.1084x over previous
#include <cuda_runtime.h>
#include <cuda_fp16.h>
#include <cstdint>

#define H 128
#define TE 128
#define NT 256

// Packed half2 weights (k, k+1) pairs along K, [kpair][N]. Static scratch.
__device__ uint32_t g_W1P[256 * 256];   // W1: K=512 -> 256 kpairs, N=256
__device__ uint32_t g_W2P[128 * 128];   // W2: K=256 -> 128 kpairs, N=128

// ---------------- helpers ----------------
__device__ __forceinline__ uint32_t smem_u32(const void* p) {
    uint32_t a;
    asm("{ .reg .u64 t; cvta.to.shared.u64 t, %1; cvt.u32.u64 %0, t; }" : "=r"(a) : "l"(p));
    return a;
}
// pack two f32 -> f16x2 (lo = first arg), single RN rounding
__device__ __forceinline__ uint32_t f2h2(float lo, float hi) {
    uint32_t r;
    asm("cvt.rn.f16x2.f32 %0, %1, %2;" : "=r"(r) : "f"(hi), "f"(lo));
    return r;
}
#define CP_ASYNC16(dst_u32, src_ptr) \
    asm volatile("cp.async.cg.shared.global [%0], [%1], 16;" :: "r"(dst_u32), "l"(src_ptr) : "memory")
#define CP_COMMIT() asm volatile("cp.async.commit_group;" ::: "memory")
#define CP_WAIT(n)  asm volatile("cp.async.wait_group %0;" :: "n"(n) : "memory")

__device__ __forceinline__ void mma16(float* c, const uint32_t* a, uint32_t b0, uint32_t b1) {
    asm volatile(
        "mma.sync.aligned.m16n8k16.row.col.f32.f16.f16.f32 "
        "{%0,%1,%2,%3}, {%4,%5,%6,%7}, {%8,%9}, {%0,%1,%2,%3};"
        : "+f"(c[0]), "+f"(c[1]), "+f"(c[2]), "+f"(c[3])
        : "r"(a[0]), "r"(a[1]), "r"(a[2]), "r"(a[3]), "r"(b0), "r"(b1));
}

// ---------------- smem layout (float offsets; pad-stride, no XOR swizzle) ----------------
#define STR_H  136   // hi/hj row stride (f32): bank = (8r + c) & 31
#define STR_B  136   // B ring row stride (u32): bank = (8R + n) & 31
#define STR_X  68    // x1 packed row stride (u32): bank = (4r + cp) & 31
#define OFF_HI 0                           // [128][STR_H] f32
#define OFF_HJ 17408                       // [128][STR_H] f32
#define OFF_R1 34816                       // L1 ring: 2 x 32 rows x STR_B u32
#define OFF_X1 43520                       // x1: [128][STR_X] u32 (half2 pairs)
#define OFF_R2 52224                       // L2 ring: 2 x 16 rows x STR_B u32
#define OFF_B1 56576                       // [256]
#define OFF_B2 56832                       // [128]
#define OFF_W3 56960                       // [256]  W3 row-major [128][2]
#define OFF_B3 57216                       // [2]
#define SMEM_FLOATS 57218
#define SMEM_BYTES (SMEM_FLOATS * 4)       // 228,872 B

// ---------------- prep: single-RN-round f32 -> packed half2 ----------------
__global__ void prep_kernel(const float* __restrict__ W1, const float* __restrict__ W2) {
    int i = blockIdx.x * blockDim.x + threadIdx.x;
    if (i < 256 * 256) {
        int kp = i >> 8, n = i & 255;
        g_W1P[i] = f2h2(W1[(2 * kp) * 256 + n], W1[(2 * kp + 1) * 256 + n]);
    } else {
        int j = i - 256 * 256;
        if (j < 128 * 128) {
            int kp = j >> 7, n = j & 127;
            g_W2P[j] = f2h2(W2[(2 * kp) * 128 + n], W2[(2 * kp + 1) * 128 + n]);
        }
    }
}

// ---------------- weight chunk prefetch ----------------
// L1 chunk c of half h into dbuf d: 32 rows (seg*8 + kpl) x 128 u32.
__device__ __forceinline__ void issue_l1(uint32_t smb, int tid, int h, int c, int d) {
    #pragma unroll
    for (int i = 0; i < 4; i++) {
        int idx = tid + i * NT;              // 0..1023
        int row = idx >> 5, n4 = idx & 31;   // row = seg*8 + kpl
        int s = row >> 3, kpl = row & 7;
        const uint32_t* srcp = g_W1P + (size_t)(s * 64 + c * 8 + kpl) * 256 + h * 128 + n4 * 4;
        uint32_t dstf = (uint32_t)(OFF_R1 + (d * 32 + row) * STR_B + n4 * 4);
        CP_ASYNC16(smb + dstf * 4, srcp);
    }
}
// L2 chunk c of half h into dbuf d: 16 rows x 128 u32.
__device__ __forceinline__ void issue_l2(uint32_t smb, int tid, int h, int c, int d) {
    #pragma unroll
    for (int i = 0; i < 2; i++) {
        int idx = tid + i * NT;              // 0..511
        int row = idx >> 5, n4 = idx & 31;
        const uint32_t* srcp = g_W2P + (size_t)(h * 64 + c * 16 + row) * 128 + n4 * 4;
        uint32_t dstf = (uint32_t)(OFF_R2 + (d * 16 + row) * STR_B + n4 * 4);
        CP_ASYNC16(smb + dstf * 4, srcp);
    }
}

// ---------------- main fused MLP ----------------
__global__ __launch_bounds__(NT, 1)
void edge_mlp_f16(const float* __restrict__ node,
                  const int*   __restrict__ src,
                  const int*   __restrict__ dst,
                  const float* __restrict__ b1,
                  const float* __restrict__ b2,
                  const float* __restrict__ W3,
                  const float* __restrict__ b3,
                  float* __restrict__ out, int E)
{
    extern __shared__ float sm[];
    const uint32_t smb = smem_u32(sm);
    uint32_t* smu = (uint32_t*)sm;

    const int tid = threadIdx.x;
    const int lane = tid & 31;
    const int g = lane >> 2, t = lane & 3;   // mma quad coords
    const int wid = tid >> 5;
    const int wm = wid >> 2, wn = wid & 3;   // warp grid 2(M) x 4(N)
    const int e0 = blockIdx.x * TE;
    const int nedge = min(TE, E - e0);

    issue_l1(smb, tid, 0, 0, 0);
    CP_COMMIT();

    // ---- gather h_i / h_j (f32, pad-stride rows; 32 threads per edge row) ----
    #pragma unroll 4
    for (int i = 0; i < 16; i++) {
        int idx = tid + i * NT;
        int m = idx >> 5, c4 = idx & 31;
        int e = min(e0 + m, E - 1);
        int si = src[e], di = dst[e];
        float4 vi = ((const float4*)node)[(size_t)si * 32 + c4];
        float4 vj = ((const float4*)node)[(size_t)di * 32 + c4];
        *(float4*)(sm + OFF_HI + m * STR_H + c4 * 4) = vi;
        *(float4*)(sm + OFF_HJ + m * STR_H + c4 * 4) = vj;
    }
    for (int i = tid; i < 256; i += NT) sm[OFF_B1 + i] = b1[i];
    for (int i = tid; i < 128; i += NT) sm[OFF_B2 + i] = b2[i];
    for (int i = tid; i < 256; i += NT) sm[OFF_W3 + i] = W3[i];
    if (tid < 2) sm[OFF_B3 + tid] = b3[tid];
    __syncthreads();

    // layer-2 accumulators, init with b2 (persist across halves)
    float accL2[64];
    #pragma unroll
    for (int mt = 0; mt < 4; mt++)
        #pragma unroll
        for (int nt = 0; nt < 4; nt++) {
            int col = wn * 32 + nt * 8 + 2 * t;
            float v0 = sm[OFF_B2 + col], v1 = sm[OFF_B2 + col + 1];
            float* A = &accL2[(mt * 4 + nt) * 4];
            A[0] = v0; A[1] = v1; A[2] = v0; A[3] = v1;
        }

    for (int h = 0; h < 2; h++) {
        // layer-1 accumulators, init with b1 slice
        float accL1[64];
        #pragma unroll
        for (int mt = 0; mt < 4; mt++)
            #pragma unroll
            for (int nt = 0; nt < 4; nt++) {
                int col = h * 128 + wn * 32 + nt * 8 + 2 * t;
                float v0 = sm[OFF_B1 + col], v1 = sm[OFF_B1 + col + 1];
                float* A = &accL1[(mt * 4 + nt) * 4];
                A[0] = v0; A[1] = v1; A[2] = v0; A[3] = v1;
            }

        // ======== layer 1: 8 chunks of 16 k (x4 segs), dbuf ========
        for (int c = 0; c < 8; c++) {
            if (c < 7) { issue_l1(smb, tid, h, c + 1, (c + 1) & 1); CP_COMMIT(); CP_WAIT(1); }
            else       { CP_WAIT(0); }
            __syncthreads();
            const int d = c & 1;
            const int cb = c * 16;

            #pragma unroll
            for (int mh = 0; mh < 2; mh++) {
                float2 P[2][4], Q[2][4];
                #pragma unroll
                for (int mi = 0; mi < 2; mi++) {
                    int r = wm * 64 + (mh * 2 + mi) * 16 + g;
                    const float* hb = sm + OFF_HI + r * STR_H + cb + 2 * t;
                    const float* jb = sm + OFF_HJ + r * STR_H + cb + 2 * t;
                    P[mi][0] = *(const float2*)(hb);
                    P[mi][1] = *(const float2*)(hb + 8 * STR_H);
                    P[mi][2] = *(const float2*)(hb + 8);
                    P[mi][3] = *(const float2*)(hb + 8 * STR_H + 8);
                    Q[mi][0] = *(const float2*)(jb);
                    Q[mi][1] = *(const float2*)(jb + 8 * STR_H);
                    Q[mi][2] = *(const float2*)(jb + 8);
                    Q[mi][3] = *(const float2*)(jb + 8 * STR_H + 8);
                }
                #pragma unroll
                for (int s = 0; s < 4; s++) {
                    uint32_t a[2][4];
                    #pragma unroll
                    for (int mi = 0; mi < 2; mi++)
                        #pragma unroll
                        for (int x = 0; x < 4; x++) {
                            float2 p = P[mi][x], q = Q[mi][x];
                            float v0, v1;
                            if      (s == 0) { v0 = p.x;              v1 = p.y; }
                            else if (s == 1) { v0 = q.x;              v1 = q.y; }
                            else if (s == 2) { v0 = fabsf(p.x - q.x); v1 = fabsf(p.y - q.y); }
                            else             { v0 = p.x * q.x;        v1 = p.y * q.y; }
                            a[mi][x] = f2h2(v0, v1);
                        }
                    const int Rb = (d * 32 + s * 8 + t) * STR_B;
                    #pragma unroll
                    for (int nt = 0; nt < 4; nt++) {
                        int n = wn * 32 + nt * 8 + g;
                        uint32_t b0 = smu[OFF_R1 + Rb + n];
                        uint32_t b1r = smu[OFF_R1 + Rb + 4 * STR_B + n];
                        mma16(&accL1[((mh * 2 + 0) * 4 + nt) * 4], a[0], b0, b1r);
                        mma16(&accL1[((mh * 2 + 1) * 4 + nt) * 4], a[1], b0, b1r);
                    }
                }
            }
            __syncthreads();
        }

        // prefetch L2 chunk0 (+ next half's L1 chunk0) while storing x1
        issue_l2(smb, tid, h, 0, 0);
        if (h == 0) issue_l1(smb, tid, 1, 0, 0);
        CP_COMMIT();

        // x1 = f16x2(relu(acc + b1)) -> packed smem (single rounding)
        #pragma unroll
        for (int mt = 0; mt < 4; mt++) {
            int r = wm * 64 + mt * 16 + g;
            #pragma unroll
            for (int nt = 0; nt < 4; nt++) {
                int cp = wn * 16 + nt * 4 + t;
                float* A = &accL1[(mt * 4 + nt) * 4];
                smu[OFF_X1 + r * STR_X + cp] =
                    f2h2(fmaxf(A[0], 0.f), fmaxf(A[1], 0.f));
                smu[OFF_X1 + (r + 8) * STR_X + cp] =
                    f2h2(fmaxf(A[2], 0.f), fmaxf(A[3], 0.f));
            }
        }
        __syncthreads();

        // ======== layer 2: 4 chunks of 32 k, dbuf ========
        for (int c = 0; c < 4; c++) {
            if (c < 3) { issue_l2(smb, tid, h, c + 1, (c + 1) & 1); CP_COMMIT(); CP_WAIT(1); }
            else       { CP_WAIT(0); }
            __syncthreads();
            const int d = c & 1;

            #pragma unroll
            for (int ks = 0; ks < 2; ks++) {
                const int cp = c * 16 + ks * 8 + t;
                uint32_t a[4][4];
                #pragma unroll
                for (int mt = 0; mt < 4; mt++) {
                    int r = wm * 64 + mt * 16 + g;
                    a[mt][0] = smu[OFF_X1 + r * STR_X + cp];
                    a[mt][1] = smu[OFF_X1 + (r + 8) * STR_X + cp];
                    a[mt][2] = smu[OFF_X1 + r * STR_X + cp + 4];
                    a[mt][3] = smu[OFF_X1 + (r + 8) * STR_X + cp + 4];
                }
                const int Rb = (d * 16 + ks * 8 + t) * STR_B;
                #pragma unroll
                for (int nt = 0; nt < 4; nt++) {
                    int n = wn * 32 + nt * 8 + g;
                    uint32_t b0 = smu[OFF_R2 + Rb + n];
                    uint32_t b1r = smu[OFF_R2 + Rb + 4 * STR_B + n];
                    #pragma unroll
                    for (int mt = 0; mt < 4; mt++)
                        mma16(&accL2[(mt * 4 + nt) * 4], a[mt], b0, b1r);
                }
            }
            __syncthreads();
        }
    }

    // ======== layer 3: register relu + W3 dot, quad shuffle-reduce ========
    float* s_red = sm + OFF_R1;   // [128 rows][4 wn][2] floats (ring is dead)
    #pragma unroll
    for (int mt = 0; mt < 4; mt++) {
        int r = wm * 64 + mt * 16 + g;
        float p00 = 0.f, p01 = 0.f, p10 = 0.f, p11 = 0.f;
        #pragma unroll
        for (int nt = 0; nt < 4; nt++) {
            float* A = &accL2[(mt * 4 + nt) * 4];
            int col = wn * 32 + nt * 8 + 2 * t;
            float w00 = sm[OFF_W3 + 2 * col],     w01 = sm[OFF_W3 + 2 * col + 1];
            float w10 = sm[OFF_W3 + 2 * col + 2], w11 = sm[OFF_W3 + 2 * col + 3];
            float x0 = fmaxf(A[0], 0.f), x1v = fmaxf(A[1], 0.f);
            float x2v = fmaxf(A[2], 0.f), x3v = fmaxf(A[3], 0.f);
            p00 += x0 * w00 + x1v * w10;
            p01 += x0 * w01 + x1v * w11;
            p10 += x2v * w00 + x3v * w10;
            p11 += x2v * w01 + x3v * w11;
        }
        p00 += __shfl_xor_sync(0xFFFFFFFFu, p00, 1);
        p00 += __shfl_xor_sync(0xFFFFFFFFu, p00, 2);
        p01 += __shfl_xor_sync(0xFFFFFFFFu, p01, 1);
        p01 += __shfl_xor_sync(0xFFFFFFFFu, p01, 2);
        p10 += __shfl_xor_sync(0xFFFFFFFFu, p10, 1);
        p10 += __shfl_xor_sync(0xFFFFFFFFu, p10, 2);
        p11 += __shfl_xor_sync(0xFFFFFFFFu, p11, 1);
        p11 += __shfl_xor_sync(0xFFFFFFFFu, p11, 2);
        if (t == 0) {
            s_red[r * 8 + wn * 2 + 0] = p00;
            s_red[r * 8 + wn * 2 + 1] = p01;
            s_red[(r + 8) * 8 + wn * 2 + 0] = p10;
            s_red[(r + 8) * 8 + wn * 2 + 1] = p11;
        }
    }
    __syncthreads();

    {
        int row = tid >> 1, cc = tid & 1;
        float sum = sm[OFF_B3 + cc]
                  + s_red[row * 8 + 0 + cc] + s_red[row * 8 + 2 + cc]
                  + s_red[row * 8 + 4 + cc] + s_red[row * 8 + 6 + cc];
        if (row < nedge) out[(size_t)(e0 + row) * 2 + cc] = sum;
    }
}

extern "C" void kernel_launch(void* const* d_in, const int* in_sizes, int n_in,
                              void* d_out, int out_size)
{
    const float* node = (const float*)d_in[0];
    const int*   src  = (const int*)  d_in[1];
    const int*   dst  = (const int*)  d_in[2];
    const float* W1   = (const float*)d_in[3];
    const float* b1   = (const float*)d_in[4];
    const float* W2   = (const float*)d_in[5];
    const float* b2   = (const float*)d_in[6];
    const float* W3   = (const float*)d_in[7];
    const float* b3   = (const float*)d_in[8];
    float* out = (float*)d_out;

    const int E = in_sizes[1];

    {
        int total = 256 * 256 + 128 * 128;
        prep_kernel<<<(total + 255) / 256, 256>>>(W1, W2);
    }

    cudaFuncSetAttribute(edge_mlp_f16,
                         cudaFuncAttributeMaxDynamicSharedMemorySize, SMEM_BYTES);

    const int grid = (E + TE - 1) / TE;
    edge_mlp_f16<<<grid, NT, SMEM_BYTES>>>(node, src, dst, b1, b2, W3, b3, out, E);
}